// round 3
// baseline (speedup 1.0000x reference)
#include <cuda_runtime.h>
#include <math.h>
#include <float.h>

// ---------------------------------------------------------------------------
// AngularLoss: loss = logsumexp_i( 4*t2*dot(a_i+p_i, n_i) - 2*(1+t2)*dot(a_i,p_i) )
// N = 262144 rows, D = 128. Pure HBM-streaming reduction (384 MiB -> 1 float).
//
// R2 -> R3 changes (theory: MLP-bound at DRAM=76%):
//   - fold linear coeffs into per-lane partial BEFORE warp reduce:
//       f_part = c1*apn_part + c2*ap_part  -> 5 SHFLs/row instead of 10
//   - unroll 4 rows/iter with all 12 LDG.128 front-batched -> MLP ~12/warp
//   - 4 interleaved shuffle chains (ILP hides 26-cyc SHFL latency)
// Fused single kernel, last-block-done final fold (deterministic order).
// ---------------------------------------------------------------------------

#define P1_BLOCKS 1184
#define P1_THREADS 256
#define WARPS_PER_BLOCK (P1_THREADS / 32)
#define UNROLL 4

__device__ float2 g_partials[P1_BLOCKS];
__device__ unsigned int g_ticket;   // zero-init; self-resets each call

__device__ __forceinline__ void lse_combine(float& m, float& s, float om, float os) {
    float nm = fmaxf(m, om);
    s = s * __expf(m - nm) + os * __expf(om - nm);
    m = nm;
}

__global__ void __launch_bounds__(P1_THREADS)
angular_fused(const float* __restrict__ A,
              const float* __restrict__ P,
              const float* __restrict__ Ng,
              const int*   __restrict__ alpha_raw,
              float* __restrict__ out,
              int N)
{
    int raw = alpha_raw[0];
    float alpha = (raw > 1000000 || raw < -1000000) ? __int_as_float(raw) : (float)raw;
    float ang = alpha * (3.14159265358979323846f / 180.0f);
    float t  = tanf(ang);
    float t2 = t * t;
    float c1 = 4.0f * t2;
    float c2 = -2.0f * (1.0f + t2);

    const float4* A4 = (const float4*)A;
    const float4* P4 = (const float4*)P;
    const float4* N4 = (const float4*)Ng;

    int lane = threadIdx.x & 31;
    int warp = threadIdx.x >> 5;
    int gwarp  = blockIdx.x * WARPS_PER_BLOCK + warp;
    int nwarps = P1_BLOCKS * WARPS_PER_BLOCK;

    float m = -FLT_MAX;
    float s = 0.0f;

    int nquads = N >> 2;   // N % 4 == 0 for this problem (guarded below anyway)

    for (int q = gwarp; q < nquads; q += nwarps) {
        int row0 = q * UNROLL;
        float4 a[UNROLL], p[UNROLL], n[UNROLL];

        // Front-batch all 12 vector loads (independent -> high MLP)
        #pragma unroll
        for (int k = 0; k < UNROLL; k++) {
            size_t base = (size_t)(row0 + k) * 32 + lane;
            a[k] = A4[base];
            p[k] = P4[base];
            n[k] = N4[base];
        }

        float fp[UNROLL];
        #pragma unroll
        for (int k = 0; k < UNROLL; k++) {
            float ap  = a[k].x * p[k].x + a[k].y * p[k].y
                      + a[k].z * p[k].z + a[k].w * p[k].w;
            float apn = (a[k].x + p[k].x) * n[k].x + (a[k].y + p[k].y) * n[k].y
                      + (a[k].z + p[k].z) * n[k].z + (a[k].w + p[k].w) * n[k].w;
            fp[k] = c1 * apn + c2 * ap;   // per-lane partial of f (linear fold)
        }

        // 4 interleaved butterfly chains (ILP)
        #pragma unroll
        for (int o = 16; o > 0; o >>= 1) {
            #pragma unroll
            for (int k = 0; k < UNROLL; k++)
                fp[k] += __shfl_xor_sync(0xFFFFFFFFu, fp[k], o);
        }

        // Online LSE, 4 updates (f identical across lanes -> no divergence)
        #pragma unroll
        for (int k = 0; k < UNROLL; k++) {
            float f = fp[k];
            if (f <= m) {
                s += __expf(f - m);
            } else {
                s = s * __expf(m - f) + 1.0f;
                m = f;
            }
        }
    }

    // Tail rows (N % 4 != 0) — none for this shape, kept for safety.
    for (int row = nquads * UNROLL + gwarp; row < N; row += nwarps) {
        size_t base = (size_t)row * 32 + lane;
        float4 a0 = A4[base], p0 = P4[base], n0 = N4[base];
        float ap  = a0.x * p0.x + a0.y * p0.y + a0.z * p0.z + a0.w * p0.w;
        float apn = (a0.x + p0.x) * n0.x + (a0.y + p0.y) * n0.y
                  + (a0.z + p0.z) * n0.z + (a0.w + p0.w) * n0.w;
        float fp0 = c1 * apn + c2 * ap;
        #pragma unroll
        for (int o = 16; o > 0; o >>= 1)
            fp0 += __shfl_xor_sync(0xFFFFFFFFu, fp0, o);
        if (fp0 <= m) { s += __expf(fp0 - m); }
        else          { s = s * __expf(m - fp0) + 1.0f; m = fp0; }
    }

    // Block reduce: lane 0 of each warp publishes (m,s); thread 0 folds.
    __shared__ float sm[WARPS_PER_BLOCK];
    __shared__ float ss[WARPS_PER_BLOCK];
    __shared__ bool s_last;
    if (lane == 0) { sm[warp] = m; ss[warp] = s; }
    __syncthreads();

    if (threadIdx.x == 0) {
        float M = -FLT_MAX, S = 0.0f;
        #pragma unroll
        for (int w = 0; w < WARPS_PER_BLOCK; w++)
            lse_combine(M, S, sm[w], ss[w]);
        g_partials[blockIdx.x] = make_float2(M, S);
        __threadfence();
        unsigned int t_old = atomicAdd(&g_ticket, 1u);
        s_last = (t_old == (unsigned int)(P1_BLOCKS - 1));
    }
    __syncthreads();

    if (!s_last) return;

    // Last block: fold all block partials in fixed index order (deterministic).
    {
        int tid = threadIdx.x;
        float fm = -FLT_MAX, fs = 0.0f;
        for (int i = tid; i < P1_BLOCKS; i += P1_THREADS) {
            float2 pp = g_partials[i];
            lse_combine(fm, fs, pp.x, pp.y);
        }
        #pragma unroll
        for (int o = 16; o > 0; o >>= 1) {
            float om = __shfl_xor_sync(0xFFFFFFFFu, fm, o);
            float os = __shfl_xor_sync(0xFFFFFFFFu, fs, o);
            lse_combine(fm, fs, om, os);
        }
        __shared__ float fsm[WARPS_PER_BLOCK];
        __shared__ float fss[WARPS_PER_BLOCK];
        if (lane == 0) { fsm[warp] = fm; fss[warp] = fs; }
        __syncthreads();
        if (threadIdx.x == 0) {
            float M = -FLT_MAX, S = 0.0f;
            #pragma unroll
            for (int w = 0; w < WARPS_PER_BLOCK; w++)
                lse_combine(M, S, fsm[w], fss[w]);
            out[0] = M + logf(S);
            g_ticket = 0;   // reset for next graph replay
        }
    }
}

extern "C" void kernel_launch(void* const* d_in, const int* in_sizes, int n_in,
                              void* d_out, int out_size)
{
    const float* A  = (const float*)d_in[0];
    const float* P  = (const float*)d_in[1];
    const float* Ng = (const float*)d_in[2];
    const int*   al = (const int*)d_in[3];
    float* out = (float*)d_out;

    int N = in_sizes[0] / 128;   // D = 128

    angular_fused<<<P1_BLOCKS, P1_THREADS>>>(A, P, Ng, al, out, N);
}

// round 6
// speedup vs baseline: 1.0397x; 1.0397x over previous
#include <cuda_runtime.h>
#include <math.h>
#include <float.h>

// ---------------------------------------------------------------------------
// AngularLoss: loss = logsumexp_i( 4*t2*dot(a_i+p_i, n_i) - 2*(1+t2)*dot(a_i,p_i) )
// N = 262144 rows, D = 128. HBM-streaming reduction (384 MiB -> 1 float).
//
// R6: (R5 minus redux.f32, which ptxas rejects on plain sm_100 target)
//   - warp-per-row, per-lane LINEAR FOLD -> ONE 5-step shuffle reduce per row
//     (vs two in the R2 baseline)
//   - depth-2 software pipeline: next row's 3 float4 issued before the
//     current row's shuffle chain -> loads always in flight
//   - __ldcs evict-first streaming loads (read-once data; spare L2)
// Fused last-block-done finish (deterministic fixed-order fold, ticket resets).
// ---------------------------------------------------------------------------

#define P1_BLOCKS 1184
#define P1_THREADS 256
#define WARPS_PER_BLOCK (P1_THREADS / 32)

__device__ float2 g_partials[P1_BLOCKS];
__device__ unsigned int g_ticket;   // zero-init; self-resets each call

__device__ __forceinline__ void lse_combine(float& m, float& s, float om, float os) {
    float nm = fmaxf(m, om);
    s = s * __expf(m - nm) + os * __expf(om - nm);
    m = nm;
}

__device__ __forceinline__ float warp_sum(float v) {
    #pragma unroll
    for (int o = 16; o > 0; o >>= 1)
        v += __shfl_xor_sync(0xFFFFFFFFu, v, o);
    return v;
}

__global__ void __launch_bounds__(P1_THREADS)
angular_fused(const float* __restrict__ A,
              const float* __restrict__ P,
              const float* __restrict__ Ng,
              const int*   __restrict__ alpha_raw,
              float* __restrict__ out,
              int N)
{
    int raw = alpha_raw[0];
    float alpha = (raw > 1000000 || raw < -1000000) ? __int_as_float(raw) : (float)raw;
    float ang = alpha * (3.14159265358979323846f / 180.0f);
    float t  = tanf(ang);
    float t2 = t * t;
    float c1 = 4.0f * t2;
    float c2 = -2.0f * (1.0f + t2);

    const float4* A4 = (const float4*)A;
    const float4* P4 = (const float4*)P;
    const float4* N4 = (const float4*)Ng;

    int lane = threadIdx.x & 31;
    int warp = threadIdx.x >> 5;
    int gwarp  = blockIdx.x * WARPS_PER_BLOCK + warp;
    int nwarps = P1_BLOCKS * WARPS_PER_BLOCK;

    float m = -FLT_MAX;
    float s = 0.0f;

    int row = gwarp;
    if (row < N) {
        size_t base = (size_t)row * 32 + lane;
        float4 a0 = __ldcs(A4 + base);
        float4 p0 = __ldcs(P4 + base);
        float4 n0 = __ldcs(N4 + base);

        for (;;) {
            int nrow = row + nwarps;
            bool have_next = (nrow < N);
            // Always issue the next loads (clamped -> valid addr) so they batch.
            size_t nbase = (size_t)(have_next ? nrow : row) * 32 + lane;
            float4 a1 = __ldcs(A4 + nbase);
            float4 p1 = __ldcs(P4 + nbase);
            float4 n1 = __ldcs(N4 + nbase);

            // Current row: per-lane partial of f (linear fold), one reduction.
            float ap  = a0.x * p0.x + a0.y * p0.y + a0.z * p0.z + a0.w * p0.w;
            float apn = (a0.x + p0.x) * n0.x + (a0.y + p0.y) * n0.y
                      + (a0.z + p0.z) * n0.z + (a0.w + p0.w) * n0.w;
            float f = warp_sum(c1 * apn + c2 * ap);

            if (f <= m) {
                s += __expf(f - m);
            } else {
                s = s * __expf(m - f) + 1.0f;
                m = f;
            }

            if (!have_next) break;
            row = nrow;
            a0 = a1; p0 = p1; n0 = n1;
        }
    }

    // Block reduce: lane 0 of each warp publishes (m,s); thread 0 folds.
    __shared__ float sm[WARPS_PER_BLOCK];
    __shared__ float ss[WARPS_PER_BLOCK];
    __shared__ bool s_last;
    if (lane == 0) { sm[warp] = m; ss[warp] = s; }
    __syncthreads();

    if (threadIdx.x == 0) {
        float M = -FLT_MAX, S = 0.0f;
        #pragma unroll
        for (int w = 0; w < WARPS_PER_BLOCK; w++)
            lse_combine(M, S, sm[w], ss[w]);
        g_partials[blockIdx.x] = make_float2(M, S);
        __threadfence();
        unsigned int t_old = atomicAdd(&g_ticket, 1u);
        s_last = (t_old == (unsigned int)(P1_BLOCKS - 1));
    }
    __syncthreads();

    if (!s_last) return;

    // Last block: fold all block partials in fixed index order (deterministic).
    {
        int tid = threadIdx.x;
        float fm = -FLT_MAX, fs = 0.0f;
        for (int i = tid; i < P1_BLOCKS; i += P1_THREADS) {
            float2 pp = g_partials[i];
            lse_combine(fm, fs, pp.x, pp.y);
        }
        #pragma unroll
        for (int o = 16; o > 0; o >>= 1) {
            float om = __shfl_xor_sync(0xFFFFFFFFu, fm, o);
            float os = __shfl_xor_sync(0xFFFFFFFFu, fs, o);
            lse_combine(fm, fs, om, os);
        }
        __shared__ float fsm[WARPS_PER_BLOCK];
        __shared__ float fss[WARPS_PER_BLOCK];
        if (lane == 0) { fsm[warp] = fm; fss[warp] = fs; }
        __syncthreads();
        if (threadIdx.x == 0) {
            float M = -FLT_MAX, S = 0.0f;
            #pragma unroll
            for (int w = 0; w < WARPS_PER_BLOCK; w++)
                lse_combine(M, S, fsm[w], fss[w]);
            out[0] = M + logf(S);
            g_ticket = 0;   // reset for next graph replay
        }
    }
}

extern "C" void kernel_launch(void* const* d_in, const int* in_sizes, int n_in,
                              void* d_out, int out_size)
{
    const float* A  = (const float*)d_in[0];
    const float* P  = (const float*)d_in[1];
    const float* Ng = (const float*)d_in[2];
    const int*   al = (const int*)d_in[3];
    float* out = (float*)d_out;

    int N = in_sizes[0] / 128;   // D = 128

    angular_fused<<<P1_BLOCKS, P1_THREADS>>>(A, P, Ng, al, out, N);
}

// round 7
// speedup vs baseline: 1.1132x; 1.0708x over previous
#include <cuda_runtime.h>
#include <math.h>
#include <float.h>

// ---------------------------------------------------------------------------
// AngularLoss: loss = logsumexp_i( 4*t2*dot(a_i+p_i, n_i) - 2*(1+t2)*dot(a_i,p_i) )
// N = 262144 rows, D = 128. HBM-streaming reduction (384 MiB -> 1 float).
//
// R7 = best-known R3-fused structure (63.9us: simple warp-per-row grid-stride
// loop, regs=32, occ 98%) with ONE change:
//   linear fold: f_part = c1*apn_part + c2*ap_part per lane, then a single
//   5-step butterfly (was two values / 10 SHFLs). Shorter chain, fewer regs.
// Lesson from R3/R6: unrolling / pipelining / __ldcs all cost registers and
// occupancy and LOWER achieved DRAM%. Keep it simple, keep occupancy maxed.
// Fused last-block-done finish (deterministic fixed-order fold, ticket resets).
// ---------------------------------------------------------------------------

#define P1_BLOCKS 1184
#define P1_THREADS 256
#define WARPS_PER_BLOCK (P1_THREADS / 32)

__device__ float2 g_partials[P1_BLOCKS];
__device__ unsigned int g_ticket;   // zero-init; self-resets each call

__device__ __forceinline__ void lse_combine(float& m, float& s, float om, float os) {
    float nm = fmaxf(m, om);
    s = s * __expf(m - nm) + os * __expf(om - nm);
    m = nm;
}

__global__ void __launch_bounds__(P1_THREADS)
angular_fused(const float* __restrict__ A,
              const float* __restrict__ P,
              const float* __restrict__ Ng,
              const int*   __restrict__ alpha_raw,
              float* __restrict__ out,
              int N)
{
    int raw = alpha_raw[0];
    float alpha = (raw > 1000000 || raw < -1000000) ? __int_as_float(raw) : (float)raw;
    float ang = alpha * (3.14159265358979323846f / 180.0f);
    float t  = tanf(ang);
    float t2 = t * t;
    float c1 = 4.0f * t2;
    float c2 = -2.0f * (1.0f + t2);

    const float4* A4 = (const float4*)A;
    const float4* P4 = (const float4*)P;
    const float4* N4 = (const float4*)Ng;

    int lane = threadIdx.x & 31;
    int warp = threadIdx.x >> 5;
    int gwarp  = blockIdx.x * WARPS_PER_BLOCK + warp;
    int nwarps = P1_BLOCKS * WARPS_PER_BLOCK;

    float m = -FLT_MAX;
    float s = 0.0f;

    for (int row = gwarp; row < N; row += nwarps) {
        size_t base = (size_t)row * 32 + lane;   // float4 index (D=128 -> 32/row)
        float4 a = A4[base];
        float4 p = P4[base];
        float4 n = N4[base];

        float ap  = a.x * p.x + a.y * p.y + a.z * p.z + a.w * p.w;
        float apn = (a.x + p.x) * n.x + (a.y + p.y) * n.y
                  + (a.z + p.z) * n.z + (a.w + p.w) * n.w;

        // Linear fold: reduce ONE value per row instead of two.
        float f = c1 * apn + c2 * ap;
        #pragma unroll
        for (int o = 16; o > 0; o >>= 1)
            f += __shfl_xor_sync(0xFFFFFFFFu, f, o);

        // Online LSE update (f identical across lanes -> no divergence)
        if (f <= m) {
            s += __expf(f - m);
        } else {
            s = s * __expf(m - f) + 1.0f;
            m = f;
        }
    }

    // Block reduce: lane 0 of each warp publishes (m,s); thread 0 folds.
    __shared__ float sm[WARPS_PER_BLOCK];
    __shared__ float ss[WARPS_PER_BLOCK];
    __shared__ bool s_last;
    if (lane == 0) { sm[warp] = m; ss[warp] = s; }
    __syncthreads();

    if (threadIdx.x == 0) {
        float M = -FLT_MAX, S = 0.0f;
        #pragma unroll
        for (int w = 0; w < WARPS_PER_BLOCK; w++)
            lse_combine(M, S, sm[w], ss[w]);
        g_partials[blockIdx.x] = make_float2(M, S);
        __threadfence();
        unsigned int t_old = atomicAdd(&g_ticket, 1u);
        s_last = (t_old == (unsigned int)(P1_BLOCKS - 1));
    }
    __syncthreads();

    if (!s_last) return;

    // Last block: fold all block partials in fixed index order (deterministic).
    {
        int tid = threadIdx.x;
        float fm = -FLT_MAX, fs = 0.0f;
        for (int i = tid; i < P1_BLOCKS; i += P1_THREADS) {
            float2 pp = g_partials[i];
            lse_combine(fm, fs, pp.x, pp.y);
        }
        #pragma unroll
        for (int o = 16; o > 0; o >>= 1) {
            float om = __shfl_xor_sync(0xFFFFFFFFu, fm, o);
            float os = __shfl_xor_sync(0xFFFFFFFFu, fs, o);
            lse_combine(fm, fs, om, os);
        }
        __shared__ float fsm[WARPS_PER_BLOCK];
        __shared__ float fss[WARPS_PER_BLOCK];
        if (lane == 0) { fsm[warp] = fm; fss[warp] = fs; }
        __syncthreads();
        if (threadIdx.x == 0) {
            float M = -FLT_MAX, S = 0.0f;
            #pragma unroll
            for (int w = 0; w < WARPS_PER_BLOCK; w++)
                lse_combine(M, S, fsm[w], fss[w]);
            out[0] = M + logf(S);
            g_ticket = 0;   // reset for next graph replay
        }
    }
}

extern "C" void kernel_launch(void* const* d_in, const int* in_sizes, int n_in,
                              void* d_out, int out_size)
{
    const float* A  = (const float*)d_in[0];
    const float* P  = (const float*)d_in[1];
    const float* Ng = (const float*)d_in[2];
    const int*   al = (const int*)d_in[3];
    float* out = (float*)d_out;

    int N = in_sizes[0] / 128;   // D = 128

    angular_fused<<<P1_BLOCKS, P1_THREADS>>>(A, P, Ng, al, out, N);
}